// round 8
// baseline (speedup 1.0000x reference)
#include <cuda_runtime.h>
#include <cuda_fp16.h>
#include <cstdint>

// Problem shape (fixed by dataset)
static constexpr int B_DIM   = 32768;
static constexpr int IN_DIM  = 64;
static constexpr int C_DIM   = 4096;

static constexpr int TM = 128;   // M tile per CTA
static constexpr int TN = 256;   // N tile per CTA (two 128-wide phases)
static constexpr int M_TILES = B_DIM / TM;   // 256
static constexpr int N_TILES = C_DIM / TN;   // 16

// SMEM: A = x fp16 [128 rows x 64 k], B = w fp16 [256 n x 64 k] (column-PERMUTED).
// Row stride padded to 72 halfs (144 B) -> conflict-free ldmatrix.
static constexpr int KP      = 72;                    // padded K stride (elements)
static constexpr int OFF_XSQ = 0;                     // 128 f32
static constexpr int OFF_WSQ = 512;                   // 256 f32 (GLOBAL col order)
static constexpr int OFF_A   = 1536;                  // 128*144 = 18432 B
static constexpr int OFF_B   = OFF_A + 128 * KP * 2;  // 19968
static constexpr int SMEM_BYTES = OFF_B + 256 * KP * 2; // 56832

// ---------------- helpers ----------------
__device__ __forceinline__ uint32_t smem_u32(const void* p) {
    uint32_t a;
    asm("{ .reg .u64 t; cvta.to.shared.u64 t, %1; cvt.u32.u64 %0, t; }" : "=r"(a) : "l"(p));
    return a;
}
__device__ __forceinline__ uint32_t pack_h2(float a, float b) {
    __half2 v(__float2half_rn(a), __float2half_rn(b));
    return *reinterpret_cast<uint32_t*>(&v);
}
__device__ __forceinline__ void ldsm_x4(uint32_t* r, uint32_t addr) {
    asm volatile("ldmatrix.sync.aligned.m8n8.x4.shared.b16 {%0,%1,%2,%3}, [%4];"
                 : "=r"(r[0]), "=r"(r[1]), "=r"(r[2]), "=r"(r[3]) : "r"(addr));
}
__device__ __forceinline__ void mma16816(float* c, const uint32_t* a, const uint32_t* b) {
    asm volatile(
        "mma.sync.aligned.m16n8k16.row.col.f32.f16.f16.f32 "
        "{%0,%1,%2,%3}, {%4,%5,%6,%7}, {%8,%9}, {%0,%1,%2,%3};"
        : "+f"(c[0]), "+f"(c[1]), "+f"(c[2]), "+f"(c[3])
        : "r"(a[0]), "r"(a[1]), "r"(a[2]), "r"(a[3]), "r"(b[0]), "r"(b[1]));
}
__device__ __forceinline__ void stg128_cs(float* p, float4 v) {
    asm volatile("st.global.cs.v4.f32 [%0], {%1,%2,%3,%4};"
                 :: "l"(p), "f"(v.x), "f"(v.y), "f"(v.z), "f"(v.w) : "memory");
}

// ---------------- main kernel ----------------
__global__ void __launch_bounds__(256, 2)
rbf_logits_kernel(const float* __restrict__ x, const float* __restrict__ w,
                  float* __restrict__ out) {
    extern __shared__ char smem[];
    const uint32_t sb = smem_u32(smem);

    const int tid  = threadIdx.x;
    const int wid  = tid >> 5;
    const int lane = tid & 31;

    const int n_tile = blockIdx.x & (N_TILES - 1);   // consecutive CTAs share x tile
    const int m_tile = blockIdx.x >> 4;              // N_TILES == 16
    const int m0 = m_tile * TM;
    const int n0 = n_tile * TN;

    float* xsq = reinterpret_cast<float*>(smem + OFF_XSQ);
    float* wsq = reinterpret_cast<float*>(smem + OFF_WSQ);

    // ---- Load + convert X tile (128 x 64 f32 -> fp16), fused x_sq ----
    {
        const float4* xv = reinterpret_cast<const float4*>(x + (size_t)m0 * IN_DIM);
#pragma unroll
        for (int j = 0; j < 8; j++) {
            int idx4 = j * 256 + tid;          // 0..2047 (16 float4 per row)
            float4 v = xv[idx4];
            int row = idx4 >> 4;
            int c4  = idx4 & 15;

            uint32_t base = OFF_A + (uint32_t)(row * KP + c4 * 4) * 2;
            *reinterpret_cast<uint2*>(smem + base) =
                make_uint2(pack_h2(v.x, v.y), pack_h2(v.z, v.w));

            float p = v.x * v.x + v.y * v.y + v.z * v.z + v.w * v.w;
            p += __shfl_xor_sync(0xFFFFFFFFu, p, 8);
            p += __shfl_xor_sync(0xFFFFFFFFu, p, 4);
            p += __shfl_xor_sync(0xFFFFFFFFu, p, 2);
            p += __shfl_xor_sync(0xFFFFFFFFu, p, 1);
            if ((lane & 15) == 0) xsq[row] = p;
        }
    }

    // ---- Load + convert W tile (256 rows, fp16, COLUMN-PERMUTED), fused w_sq ----
    // Global col g -> tile row (g & ~15) | ((g&1)<<3) | ((g>>1)&7): interleaves
    // adjacent n8 fragments so epilogue lanes own 4 consecutive global columns.
    {
        const float4* wv = reinterpret_cast<const float4*>(w + (size_t)n0 * IN_DIM);
#pragma unroll
        for (int j = 0; j < 16; j++) {
            int idx4 = j * 256 + tid;          // 0..4095
            float4 v = wv[idx4];
            int row = idx4 >> 4;               // 0..255 global n in tile
            int c4  = idx4 & 15;
            int trow = (row & ~15) | ((row & 1) << 3) | ((row >> 1) & 7);

            uint32_t base = OFF_B + (uint32_t)(trow * KP + c4 * 4) * 2;
            *reinterpret_cast<uint2*>(smem + base) =
                make_uint2(pack_h2(v.x, v.y), pack_h2(v.z, v.w));

            float p = v.x * v.x + v.y * v.y + v.z * v.z + v.w * v.w;
            p += __shfl_xor_sync(0xFFFFFFFFu, p, 8);
            p += __shfl_xor_sync(0xFFFFFFFFu, p, 4);
            p += __shfl_xor_sync(0xFFFFFFFFu, p, 2);
            p += __shfl_xor_sync(0xFFFFFFFFu, p, 1);
            if ((lane & 15) == 0) wsq[row] = p;   // GLOBAL col order
        }
    }

    __syncthreads();

    // ---- Warp tiling: 8 warps = 4 (M) x 2 (N); warp tile 32 x 64 per phase ----
    const int m_warp = (wid >> 1) * 32;
    const int n_warp = (wid & 1) * 64;

    // A (row-major, m16k16 tiles): lane i -> row (i&15), k-half (i>>4)*8
    uint32_t a_addr0 = sb + OFF_A +
        ((uint32_t)(m_warp +      (lane & 15)) * KP + ((lane >> 4) * 8)) * 2;
    uint32_t a_addr1 = a_addr0 + 16u * KP * 2;
    // B ([n][k] row-major, NON-trans): mma B frag wants lane l -> (n=l>>2, k=(l&3)*2)
    uint32_t b_addr = sb + OFF_B +
        ((uint32_t)(n_warp + ((lane >> 4) << 3) + (lane & 7)) * KP +
         (((lane >> 3) & 1) * 8)) * 2;

    // ---- Cache ALL A fragments in registers (reused across both N-phases) ----
    uint32_t afr[2][4][4];                       // [mt][ks][reg]
#pragma unroll
    for (int ks = 0; ks < 4; ks++) {
        const uint32_t koff = (uint32_t)ks * 16 * 2;
        ldsm_x4(afr[0][ks], a_addr0 + koff);
        ldsm_x4(afr[1][ks], a_addr1 + koff);
    }

    const int q  = lane & 3;
    const int rl = lane >> 2;
    const float xs[4] = {
        xsq[m_warp +      rl],  xsq[m_warp +      rl + 8],
        xsq[m_warp + 16 + rl],  xsq[m_warp + 16 + rl + 8],
    };

#pragma unroll
    for (int ph = 0; ph < 2; ph++) {
        const uint32_t b_ph = b_addr + (uint32_t)ph * 128 * KP * 2;

        float acc[2][8][4];
#pragma unroll
        for (int mt = 0; mt < 2; mt++)
#pragma unroll
            for (int nt = 0; nt < 8; nt++)
#pragma unroll
                for (int t = 0; t < 4; t++) acc[mt][nt][t] = 0.0f;

#pragma unroll
        for (int ks = 0; ks < 4; ks++) {          // K = 64 in steps of 16
            const uint32_t koff = (uint32_t)ks * 16 * 2;
            uint32_t b[8][2];
#pragma unroll
            for (int p = 0; p < 4; p++) {
                uint32_t r[4];
                ldsm_x4(r, b_ph + (uint32_t)p * 16 * KP * 2 + koff);
                b[2 * p][0] = r[0]; b[2 * p][1] = r[1];
                b[2 * p + 1][0] = r[2]; b[2 * p + 1][1] = r[3];
            }
#pragma unroll
            for (int nt = 0; nt < 8; nt++) {
                mma16816(acc[0][nt], afr[0][ks], b[nt]);
                mma16816(acc[1][nt], afr[1][ks], b[nt]);
            }
        }

        // ---- Epilogue: logits = 2*cross - x_sq - w_sq, float4 register stores ----
        // Permutation: frag 2p col c -> global 2c, frag 2p+1 -> 2c+1. Lane q owns
        // frag cols 2q,2q+1 of both => global cols p*16 + 4q..4q+3 (64B/quad).
#pragma unroll
        for (int mt = 0; mt < 2; mt++) {
#pragma unroll
            for (int p = 0; p < 4; p++) {
                const float* a = acc[mt][2 * p];       // even global cols
                const float* b = acc[mt][2 * p + 1];   // odd  global cols
                const int cbase = ph * 128 + n_warp + p * 16 + q * 4;
                const float4 wq = *reinterpret_cast<const float4*>(wsq + cbase);

                const size_t r0 = (size_t)(m0 + m_warp + mt * 16 + rl);
                const float xs0 = xs[mt * 2], xs1 = xs[mt * 2 + 1];

                float4 v0;
                v0.x = fmaf(2.0f, a[0], -(xs0 + wq.x));
                v0.y = fmaf(2.0f, b[0], -(xs0 + wq.y));
                v0.z = fmaf(2.0f, a[1], -(xs0 + wq.z));
                v0.w = fmaf(2.0f, b[1], -(xs0 + wq.w));
                stg128_cs(out + r0 * C_DIM + (n0 + cbase), v0);

                float4 v1;
                v1.x = fmaf(2.0f, a[2], -(xs1 + wq.x));
                v1.y = fmaf(2.0f, b[2], -(xs1 + wq.y));
                v1.z = fmaf(2.0f, a[3], -(xs1 + wq.z));
                v1.w = fmaf(2.0f, b[3], -(xs1 + wq.w));
                stg128_cs(out + (r0 + 8) * C_DIM + (n0 + cbase), v1);
            }
        }
    }
}

extern "C" void kernel_launch(void* const* d_in, const int* in_sizes, int n_in,
                              void* d_out, int out_size) {
    const float* x = reinterpret_cast<const float*>(d_in[0]);
    const float* w = reinterpret_cast<const float*>(d_in[1]);
    // Defensive: identify by size (x has B*64 elements, w has C*64)
    if (n_in >= 2 && in_sizes[0] == C_DIM * IN_DIM && in_sizes[1] == B_DIM * IN_DIM) {
        const float* t = x; x = w; w = t;
    }
    float* out = reinterpret_cast<float*>(d_out);

    cudaFuncSetAttribute(rbf_logits_kernel,
                         cudaFuncAttributeMaxDynamicSharedMemorySize, SMEM_BYTES);
    rbf_logits_kernel<<<M_TILES * N_TILES, 256, SMEM_BYTES>>>(x, w, out);
}

// round 9
// speedup vs baseline: 1.4635x; 1.4635x over previous
#include <cuda_runtime.h>
#include <cuda_fp16.h>
#include <cstdint>

// Problem shape (fixed by dataset)
static constexpr int B_DIM   = 32768;
static constexpr int IN_DIM  = 64;
static constexpr int C_DIM   = 4096;

static constexpr int TM = 128;   // M tile per iteration
static constexpr int M_SUB = 2;  // M iterations per CTA (w tile reused)
static constexpr int TN = 128;   // N tile per CTA
static constexpr int M_TILES = B_DIM / (TM * M_SUB);  // 128
static constexpr int N_TILES = C_DIM / TN;            // 32

// SMEM: A = x fp16 [128 rows x 64 k], B = w fp16 [128 n x 64 k] (column-PERMUTED).
// Row stride padded to 72 halfs (144 B) -> conflict-free ldmatrix.
static constexpr int KP      = 72;                   // padded K stride (elements)
static constexpr int OFF_XSQ = 0;                    // 128 f32
static constexpr int OFF_WSQ = 512;                  // 128 f32 (GLOBAL col order)
static constexpr int OFF_A   = 1024;                 // 128*144 B = 18432
static constexpr int OFF_B   = OFF_A + 128 * KP * 2; // 19456
static constexpr int SMEM_BYTES = OFF_B + 128 * KP * 2; // 37888

// ---------------- helpers ----------------
__device__ __forceinline__ uint32_t smem_u32(const void* p) {
    uint32_t a;
    asm("{ .reg .u64 t; cvta.to.shared.u64 t, %1; cvt.u32.u64 %0, t; }" : "=r"(a) : "l"(p));
    return a;
}
__device__ __forceinline__ uint32_t pack_h2(float a, float b) {
    __half2 v(__float2half_rn(a), __float2half_rn(b));
    return *reinterpret_cast<uint32_t*>(&v);
}
__device__ __forceinline__ void ldsm_x4(uint32_t* r, uint32_t addr) {
    asm volatile("ldmatrix.sync.aligned.m8n8.x4.shared.b16 {%0,%1,%2,%3}, [%4];"
                 : "=r"(r[0]), "=r"(r[1]), "=r"(r[2]), "=r"(r[3]) : "r"(addr));
}
__device__ __forceinline__ void mma16816(float* c, const uint32_t* a, const uint32_t* b) {
    asm volatile(
        "mma.sync.aligned.m16n8k16.row.col.f32.f16.f16.f32 "
        "{%0,%1,%2,%3}, {%4,%5,%6,%7}, {%8,%9}, {%0,%1,%2,%3};"
        : "+f"(c[0]), "+f"(c[1]), "+f"(c[2]), "+f"(c[3])
        : "r"(a[0]), "r"(a[1]), "r"(a[2]), "r"(a[3]), "r"(b[0]), "r"(b[1]));
}
__device__ __forceinline__ void stg128_cs(float* p, float4 v) {
    asm volatile("st.global.cs.v4.f32 [%0], {%1,%2,%3,%4};"
                 :: "l"(p), "f"(v.x), "f"(v.y), "f"(v.z), "f"(v.w) : "memory");
}

// ---------------- main kernel ----------------
__global__ void __launch_bounds__(256, 2)
rbf_logits_kernel(const float* __restrict__ x, const float* __restrict__ w,
                  float* __restrict__ out) {
    extern __shared__ char smem[];
    const uint32_t sb = smem_u32(smem);

    const int tid  = threadIdx.x;
    const int wid  = tid >> 5;
    const int lane = tid & 31;

    const int n_tile = blockIdx.x & (N_TILES - 1);   // consecutive CTAs share x tiles
    const int m_tile = blockIdx.x >> 5;              // N_TILES == 32
    const int n0 = n_tile * TN;

    float* xsq = reinterpret_cast<float*>(smem + OFF_XSQ);
    float* wsq = reinterpret_cast<float*>(smem + OFF_WSQ);

    // ---- Load + convert W tile ONCE (fp16, COLUMN-PERMUTED rows), fused w_sq ----
    // Global col g -> tile row (g&0x70) | ((g&1)<<3) | ((g>>1)&7): interleaves two
    // adjacent n8 fragments so epilogue lanes own 4 consecutive global columns.
    {
        const float4* wv = reinterpret_cast<const float4*>(w + (size_t)n0 * IN_DIM);
#pragma unroll
        for (int j = 0; j < 8; j++) {
            int idx4 = j * 256 + tid;
            float4 v = wv[idx4];
            int row = idx4 >> 4;               // global n index in tile
            int c4  = idx4 & 15;
            int trow = (row & 0x70) | ((row & 1) << 3) | ((row >> 1) & 7);

            uint32_t base = OFF_B + (uint32_t)(trow * KP + c4 * 4) * 2;
            *reinterpret_cast<uint2*>(smem + base) =
                make_uint2(pack_h2(v.x, v.y), pack_h2(v.z, v.w));

            float p = v.x * v.x + v.y * v.y + v.z * v.z + v.w * v.w;
            p += __shfl_xor_sync(0xFFFFFFFFu, p, 8);
            p += __shfl_xor_sync(0xFFFFFFFFu, p, 4);
            p += __shfl_xor_sync(0xFFFFFFFFu, p, 2);
            p += __shfl_xor_sync(0xFFFFFFFFu, p, 1);
            if ((lane & 15) == 0) wsq[row] = p;   // GLOBAL col order
        }
    }

    // ---- Warp tiling: 8 warps = 4 (M) x 2 (N); warp tile = 32 x 64 ----
    const int m_warp = (wid >> 1) * 32;
    const int n_warp = (wid & 1) * 64;

    // A (row-major, m16k16 tiles): lane i -> row (i&15), k-half (i>>4)*8
    const uint32_t a_addr0 = sb + OFF_A +
        ((uint32_t)(m_warp +      (lane & 15)) * KP + ((lane >> 4) * 8)) * 2;
    const uint32_t a_addr1 = a_addr0 + 16u * KP * 2;
    // B ([n][k] row-major, NON-trans): mma B frag wants lane l -> (n=l>>2, k=(l&3)*2)
    const uint32_t b_addr = sb + OFF_B +
        ((uint32_t)(n_warp + ((lane >> 4) << 3) + (lane & 7)) * KP +
         (((lane >> 3) & 1) * 8)) * 2;

    const int q  = lane & 3;
    const int rl = lane >> 2;

    for (int sub = 0; sub < M_SUB; sub++) {
        const int m0 = (m_tile * M_SUB + sub) * TM;

        if (sub > 0) __syncthreads();   // prior iter's LDSM/xsq reads done before rewrite

        // ---- Load + convert X tile (128 x 64 f32 -> fp16), fused x_sq ----
        {
            const float4* xv = reinterpret_cast<const float4*>(x + (size_t)m0 * IN_DIM);
#pragma unroll
            for (int j = 0; j < 8; j++) {
                int idx4 = j * 256 + tid;          // 0..2047 (16 float4 per row)
                float4 v = xv[idx4];
                int row = idx4 >> 4;
                int c4  = idx4 & 15;

                uint32_t base = OFF_A + (uint32_t)(row * KP + c4 * 4) * 2;
                *reinterpret_cast<uint2*>(smem + base) =
                    make_uint2(pack_h2(v.x, v.y), pack_h2(v.z, v.w));

                float p = v.x * v.x + v.y * v.y + v.z * v.z + v.w * v.w;
                p += __shfl_xor_sync(0xFFFFFFFFu, p, 8);
                p += __shfl_xor_sync(0xFFFFFFFFu, p, 4);
                p += __shfl_xor_sync(0xFFFFFFFFu, p, 2);
                p += __shfl_xor_sync(0xFFFFFFFFu, p, 1);
                if ((lane & 15) == 0) xsq[row] = p;
            }
        }

        __syncthreads();

        float acc[2][8][4];
#pragma unroll
        for (int mt = 0; mt < 2; mt++)
#pragma unroll
            for (int nt = 0; nt < 8; nt++)
#pragma unroll
                for (int t = 0; t < 4; t++) acc[mt][nt][t] = 0.0f;

#pragma unroll
        for (int ks = 0; ks < 4; ks++) {          // K = 64 in steps of 16
            const uint32_t koff = (uint32_t)ks * 16 * 2;
            uint32_t a0[4], a1[4];
            ldsm_x4(a0, a_addr0 + koff);
            ldsm_x4(a1, a_addr1 + koff);
            uint32_t b[8][2];
#pragma unroll
            for (int p = 0; p < 4; p++) {
                uint32_t r[4];
                ldsm_x4(r, b_addr + (uint32_t)p * 16 * KP * 2 + koff);
                b[2 * p][0] = r[0]; b[2 * p][1] = r[1];
                b[2 * p + 1][0] = r[2]; b[2 * p + 1][1] = r[3];
            }
#pragma unroll
            for (int nt = 0; nt < 8; nt++) {
                mma16816(acc[0][nt], a0, b[nt]);
                mma16816(acc[1][nt], a1, b[nt]);
            }
        }

        // ---- Epilogue: logits = 2*cross - x_sq - w_sq, float4 register stores ----
        // Permutation: frag 2p col c -> global p*16+2c, frag 2p+1 -> p*16+2c+1.
        // Lane q owns frag cols 2q,2q+1 of both => global cols p*16+4q..4q+3.
        const float xs[4] = {
            xsq[m_warp +      rl],  xsq[m_warp +      rl + 8],
            xsq[m_warp + 16 + rl],  xsq[m_warp + 16 + rl + 8],
        };

#pragma unroll
        for (int mt = 0; mt < 2; mt++) {
#pragma unroll
            for (int p = 0; p < 4; p++) {
                const float* a = acc[mt][2 * p];       // even global cols
                const float* b = acc[mt][2 * p + 1];   // odd  global cols
                const int cbase = n_warp + p * 16 + q * 4;
                const float4 wq = *reinterpret_cast<const float4*>(wsq + cbase);

                const size_t r0 = (size_t)(m0 + m_warp + mt * 16 + rl);
                const float xs0 = xs[mt * 2], xs1 = xs[mt * 2 + 1];

                float4 v0;
                v0.x = fmaf(2.0f, a[0], -(xs0 + wq.x));
                v0.y = fmaf(2.0f, b[0], -(xs0 + wq.y));
                v0.z = fmaf(2.0f, a[1], -(xs0 + wq.z));
                v0.w = fmaf(2.0f, b[1], -(xs0 + wq.w));
                stg128_cs(out + r0 * C_DIM + (n0 + cbase), v0);

                float4 v1;
                v1.x = fmaf(2.0f, a[2], -(xs1 + wq.x));
                v1.y = fmaf(2.0f, b[2], -(xs1 + wq.y));
                v1.z = fmaf(2.0f, a[3], -(xs1 + wq.z));
                v1.w = fmaf(2.0f, b[3], -(xs1 + wq.w));
                stg128_cs(out + (r0 + 8) * C_DIM + (n0 + cbase), v1);
            }
        }
    }
}

extern "C" void kernel_launch(void* const* d_in, const int* in_sizes, int n_in,
                              void* d_out, int out_size) {
    const float* x = reinterpret_cast<const float*>(d_in[0]);
    const float* w = reinterpret_cast<const float*>(d_in[1]);
    // Defensive: identify by size (x has B*64 elements, w has C*64)
    if (n_in >= 2 && in_sizes[0] == C_DIM * IN_DIM && in_sizes[1] == B_DIM * IN_DIM) {
        const float* t = x; x = w; w = t;
    }
    float* out = reinterpret_cast<float*>(d_out);

    cudaFuncSetAttribute(rbf_logits_kernel,
                         cudaFuncAttributeMaxDynamicSharedMemorySize, SMEM_BYTES);
    rbf_logits_kernel<<<M_TILES * N_TILES, 256, SMEM_BYTES>>>(x, w, out);
}